// round 2
// baseline (speedup 1.0000x reference)
#include <cuda_runtime.h>
#include <math.h>
#include <stdint.h>

#define BB 8
#define SS 512
#define NSPAN 512
#define H 768
#define NH 4
#define HD 192
#define FFN_DIM 3072
#define LSPAN 32
#define BS (BB*SS)      // 4096 token rows
#define BN (BB*NSPAN)   // 4096 span rows

// ---------------- scratch (static device globals; no allocations) ----------
__device__ float g_X[BS*H];           // tokens + positional encoding
__device__ float g_KV[(size_t)BS*2*H];// per-token K (cols 0..767) and V (768..1535)
__device__ float g_qc[H];             // projected query
__device__ float g_bias2[H];          // out_b + dummy_query (fused epilogue bias)
__device__ float g_ctx[(size_t)BN*H];
__device__ float g_ao[(size_t)BN*H];
__device__ float g_y[(size_t)BN*H];
__device__ float g_h1[(size_t)BN*FFN_DIM];
__device__ float g_ff[(size_t)BN*H];

// ---------------- kernel 1: X = token_reps + sinusoidal PE -----------------
__global__ void add_pe_kernel(const float* __restrict__ tok) {
    int idx = blockIdx.x * blockDim.x + threadIdx.x;
    if (idx >= BS * H) return;
    int d   = idx % H;
    int row = idx / H;
    int pos = row % SS;
    int i2  = d & ~1;                      // 0,0,2,2,4,4,...
    const float c = (float)(-9.210340371976184 / (double)H); // -ln(10000)/H
    float freq = expf((float)i2 * c);
    float ang  = (float)pos * freq;
    float pe   = (d & 1) ? cosf(ang) : sinf(ang);
    g_X[idx] = tok[idx] + pe;
}

// ---------------- kernel 2: q projection + fused bias ----------------------
__global__ void proj_q_kernel(const float* __restrict__ dq,
                              const float* __restrict__ in_w,
                              const float* __restrict__ in_b,
                              const float* __restrict__ out_b) {
    int o = blockIdx.x * blockDim.x + threadIdx.x;
    if (o >= H) return;
    const float* wr = in_w + (size_t)o * H;   // Wq row o
    float acc = in_b[o];
    #pragma unroll 4
    for (int c = 0; c < H; c++) acc += dq[c] * wr[c];
    g_qc[o]    = acc;
    g_bias2[o] = out_b[o] + dq[o];            // attn_out + dummy_query residual
}

// ---------------- tiled SGEMM: C[M,N] = A[M,K] @ W[N,K]^T + bias -----------
// BM=128, BN=64, BK=16, 256 threads, 8x4 micro-tile. All dims divide evenly.
template<bool RELU>
__global__ void sgemm_nt(const float* __restrict__ A, const float* __restrict__ W,
                         const float* __restrict__ bias, float* __restrict__ C,
                         int M, int N, int K) {
    __shared__ float As[16][128];
    __shared__ float Bs[16][64];
    int tid = threadIdx.x;
    int m0  = blockIdx.y * 128;
    int n0  = blockIdx.x * 64;
    int tx  = tid & 15;    // -> 4 cols
    int ty  = tid >> 4;    // -> 8 rows

    float acc[8][4];
    #pragma unroll
    for (int i = 0; i < 8; i++)
        #pragma unroll
        for (int j = 0; j < 4; j++) acc[i][j] = 0.f;

    for (int k0 = 0; k0 < K; k0 += 16) {
        #pragma unroll
        for (int r = 0; r < 2; r++) {
            int lin = tid + r * 256;
            int row = lin >> 2;           // 0..127
            int cv  = (lin & 3) << 2;     // 0,4,8,12
            float4 v = *reinterpret_cast<const float4*>(&A[(size_t)(m0 + row) * K + k0 + cv]);
            As[cv + 0][row] = v.x; As[cv + 1][row] = v.y;
            As[cv + 2][row] = v.z; As[cv + 3][row] = v.w;
        }
        {
            int row = tid >> 2;           // 0..63
            int cv  = (tid & 3) << 2;
            float4 v = *reinterpret_cast<const float4*>(&W[(size_t)(n0 + row) * K + k0 + cv]);
            Bs[cv + 0][row] = v.x; Bs[cv + 1][row] = v.y;
            Bs[cv + 2][row] = v.z; Bs[cv + 3][row] = v.w;
        }
        __syncthreads();
        #pragma unroll
        for (int kk = 0; kk < 16; kk++) {
            float a[8], b[4];
            #pragma unroll
            for (int i = 0; i < 8; i++) a[i] = As[kk][ty * 8 + i];
            #pragma unroll
            for (int j = 0; j < 4; j++) b[j] = Bs[kk][tx * 4 + j];
            #pragma unroll
            for (int i = 0; i < 8; i++)
                #pragma unroll
                for (int j = 0; j < 4; j++) acc[i][j] += a[i] * b[j];
        }
        __syncthreads();
    }

    #pragma unroll
    for (int i = 0; i < 8; i++) {
        int mrow = m0 + ty * 8 + i;
        #pragma unroll
        for (int j = 0; j < 4; j++) {
            int ncol = n0 + tx * 4 + j;
            float v = acc[i][j] + bias[ncol];
            if (RELU) v = fmaxf(v, 0.f);
            C[(size_t)mrow * N + ncol] = v;
        }
    }
}

// ---------------- attention: 1 block per span, warp per head ---------------
__global__ void attn_kernel(const int* __restrict__ span_ids,
                            const int* __restrict__ masks) {
    int span = blockIdx.x;           // 0..BN-1
    int b    = span / NSPAN;
    __shared__ float sq[H];
    __shared__ float sattn[NH][LSPAN];
    __shared__ int sh_start, sh_len;

    int tid = threadIdx.x;           // 128 threads
    if (tid == 0) {
        int st = span_ids[span * 2 + 0];
        int en = span_ids[span * 2 + 1];
        int mk = masks[span] ? 1 : 0;
        sh_start = st;
        sh_len   = (en - st) * mk;
    }
    for (int i = tid; i < H; i += 128) sq[i] = g_qc[i];
    __syncthreads();

    int start = sh_start, len = sh_len;
    int h = tid >> 5;                // warp id = head
    int l = tid & 31;                // lane = key position

    const float scale = 1.0f / sqrtf((float)HD);
    float score = -INFINITY;
    if (l < len) {
        const float* kr = g_KV + ((size_t)(b * SS + start + l)) * (2 * H) + h * HD;
        const float* qh = sq + h * HD;
        float acc = 0.f;
        #pragma unroll
        for (int d = 0; d < HD; d += 4) {
            float4 k4 = *reinterpret_cast<const float4*>(kr + d);
            acc += qh[d] * k4.x + qh[d + 1] * k4.y + qh[d + 2] * k4.z + qh[d + 3] * k4.w;
        }
        score = acc * scale;
    }
    // warp softmax over 32 key slots
    float mx = score;
    #pragma unroll
    for (int o = 16; o > 0; o >>= 1) mx = fmaxf(mx, __shfl_xor_sync(0xffffffffu, mx, o));
    float e = (l < len) ? expf(score - mx) : 0.f;
    float sum = e;
    #pragma unroll
    for (int o = 16; o > 0; o >>= 1) sum += __shfl_xor_sync(0xffffffffu, sum, o);
    sattn[h][l] = (sum > 0.f) ? (e / sum) : 0.f;
    __syncthreads();

    // ctx[h*HD + d] = sum_l attn[h][l] * V[start+l, h*HD+d]; coalesced over o
    const float* rowbase = g_KV + ((size_t)(b * SS + start)) * (2 * H) + H;
    for (int o = tid; o < H; o += 128) {
        int hh = o / HD;
        float acc = 0.f;
        const float* vp = rowbase + o;
        for (int l2 = 0; l2 < len; l2++)
            acc += sattn[hh][l2] * vp[(size_t)l2 * 2 * H];
        g_ctx[(size_t)span * H + o] = acc;
    }
}

// ---------------- LayerNorm (block per row), optional residual + mask ------
__global__ void ln_kernel(const float* __restrict__ in, const float* __restrict__ res,
                          const float* __restrict__ gam, const float* __restrict__ bet,
                          float* __restrict__ out, const int* __restrict__ masks,
                          int has_res, int mask_out) {
    int row = blockIdx.x;
    __shared__ float sv[H];
    __shared__ float red[8];
    int tid = threadIdx.x;           // 256

    float s = 0.f;
    for (int i = tid; i < H; i += 256) {
        float v = in[(size_t)row * H + i];
        if (has_res) v += res[(size_t)row * H + i];
        sv[i] = v;
        s += v;
    }
    #pragma unroll
    for (int o = 16; o > 0; o >>= 1) s += __shfl_xor_sync(0xffffffffu, s, o);
    if ((tid & 31) == 0) red[tid >> 5] = s;
    __syncthreads();
    float tot = 0.f;
    #pragma unroll
    for (int w = 0; w < 8; w++) tot += red[w];
    float mean = tot / (float)H;
    __syncthreads();

    float vs = 0.f;
    for (int i = tid; i < H; i += 256) {
        float d = sv[i] - mean;
        vs += d * d;
    }
    #pragma unroll
    for (int o = 16; o > 0; o >>= 1) vs += __shfl_xor_sync(0xffffffffu, vs, o);
    if ((tid & 31) == 0) red[tid >> 5] = vs;
    __syncthreads();
    float vtot = 0.f;
    #pragma unroll
    for (int w = 0; w < 8; w++) vtot += red[w];
    float rstd = rsqrtf(vtot / (float)H + 1e-5f);

    int keep = mask_out ? (masks[row] ? 1 : 0) : 1;
    for (int i = tid; i < H; i += 256) {
        float val = (sv[i] - mean) * rstd * gam[i] + bet[i];
        out[(size_t)row * H + i] = keep ? val : 0.f;
    }
}

// ---------------- launch ---------------------------------------------------
extern "C" void kernel_launch(void* const* d_in, const int* in_sizes, int n_in,
                              void* d_out, int out_size) {
    const float* tok   = (const float*)d_in[0];
    const int*   sids  = (const int*)d_in[1];
    const int*   masks = (const int*)d_in[2];    // bool -> int32 on the wire
    // 'pooling' scalar may or may not be passed as an input — handle both.
    int base = (n_in >= 15) ? 4 : 3;
    const float* dq    = (const float*)d_in[base + 0];
    const float* in_w  = (const float*)d_in[base + 1];
    const float* in_b  = (const float*)d_in[base + 2];
    const float* out_w = (const float*)d_in[base + 3];
    const float* out_b = (const float*)d_in[base + 4];
    const float* ln_g  = (const float*)d_in[base + 5];
    const float* ln_b  = (const float*)d_in[base + 6];
    const float* w1    = (const float*)d_in[base + 7];
    const float* b1    = (const float*)d_in[base + 8];
    const float* w2    = (const float*)d_in[base + 9];
    const float* b2    = (const float*)d_in[base + 10];
    float* outp = (float*)d_out;

    // resolve device-global scratch addresses (host side)
    float *pX, *pKV, *pCtx, *pAo, *pY, *pH1, *pFf, *pQc, *pBias2;
    cudaGetSymbolAddress((void**)&pX,     g_X);
    cudaGetSymbolAddress((void**)&pKV,    g_KV);
    cudaGetSymbolAddress((void**)&pCtx,   g_ctx);
    cudaGetSymbolAddress((void**)&pAo,    g_ao);
    cudaGetSymbolAddress((void**)&pY,     g_y);
    cudaGetSymbolAddress((void**)&pH1,    g_h1);
    cudaGetSymbolAddress((void**)&pFf,    g_ff);
    cudaGetSymbolAddress((void**)&pQc,    g_qc);
    cudaGetSymbolAddress((void**)&pBias2, g_bias2);

    // 1. X = tokens + PE
    add_pe_kernel<<<(BS * H + 255) / 256, 256>>>(tok);
    // 2. q projection + fused residual bias
    proj_q_kernel<<<3, 256>>>(dq, in_w, in_b, out_b);
    // 3. per-token KV projection: [4096,1536] = X @ Wkv^T + bkv
    sgemm_nt<false><<<dim3(1536 / 64, BS / 128), 256>>>(
        pX, in_w + (size_t)H * H, in_b + H, pKV, BS, 2 * H, H);
    // 4. span attention -> ctx
    attn_kernel<<<BN, 128>>>(sids, masks);
    // 5. out projection (+ out_b + dummy_query via fused bias)
    sgemm_nt<false><<<dim3(H / 64, BN / 128), 256>>>(
        pCtx, out_w, pBias2, pAo, BN, H, H);
    // 6. LN1
    ln_kernel<<<BN, 256>>>(pAo, nullptr, ln_g, ln_b, pY, nullptr, 0, 0);
    // 7. FFN1 + relu
    sgemm_nt<true><<<dim3(FFN_DIM / 64, BN / 128), 256>>>(
        pY, w1, b1, pH1, BN, FFN_DIM, H);
    // 8. FFN2
    sgemm_nt<false><<<dim3(H / 64, BN / 128), 256>>>(
        pH1, w2, b2, pFf, BN, H, FFN_DIM);
    // 9. LN2 (+ residual y, + span mask) -> output
    ln_kernel<<<BN, 256>>>(pFf, pY, ln_g, ln_b, outp, masks, 1, 1);
    (void)in_sizes; (void)out_size;
}